// round 6
// baseline (speedup 1.0000x reference)
#include <cuda_runtime.h>
#include <cstddef>

#define HH 128
#define WW 128
#define HWSZ (HH*WW)
#define EBN 8      // B(2) * 4 non-center frames, processed concurrently
#define CF 64
#define COFF 144
#define WSTEP (CF*CF*9)

// ---------------- scratch (device globals; no allocation) ----------------
__device__ float g_fea0[(size_t)EBN*CF*HWSZ];   // 32 MB
__device__ float g_fea1[(size_t)EBN*CF*HWSZ];   // 32 MB
__device__ float g_off [(size_t)EBN*COFF*HWSZ]; // 72 MB
__device__ float g_wT  [4*WSTEP];               // transposed dconv weights

// scratch selector (device-side; keeps host code API-free)
__device__ __forceinline__ float* scratch_ptr(int sel) {
    return sel == 0 ? g_fea0 : (sel == 1 ? g_fea1 : g_off);
}

// eb -> (b, frame)
__device__ __forceinline__ void eb_map(int eb, int& b, int& fi) {
    b = eb >> 2;
    int f = eb & 3;
    fi = f + (f >= 2 ? 1 : 0);   // frames {0,1,3,4}
}

// ---------------- generic 3x3 SAME conv ----------------
// inMode: 0 = scratch[inSel] + eb*Cin*HW
//         1 = concat(ref, supp) read from pf (ext_in = pf base)
// outMode:0 = scratch[outSel] + eb*Cout*HW
//         1 = final output: ext_out + (b*5+fi)*3*HW
__global__ void __launch_bounds__(256) conv3x3_kernel(
    const float* __restrict__ ext_in,
    const float* __restrict__ w,
    const float* __restrict__ bias,
    float* __restrict__ ext_out,
    int Cin, int Cout, int inMode, int outMode, int inSel, int outSel)
{
    __shared__ float s_in[8][18][34];
    __shared__ float s_w[16][8][9];

    int tid = threadIdx.x;
    int tx = tid & 31, ty = tid >> 5;           // 32 x 8 threads, 2 rows/thread
    int ocg = (Cout + 15) >> 4;
    int eb = blockIdx.z / ocg;
    int ocBase = (blockIdx.z % ocg) << 4;
    int b, fi; eb_map(eb, b, fi);
    int ox0 = blockIdx.x * 32, oy0 = blockIdx.y * 16;

    const float* ref = nullptr; const float* supp = nullptr; const float* inb = nullptr;
    if (inMode == 1) {
        ref  = ext_in + (size_t)(b*5 + 2)  * CF * HWSZ;
        supp = ext_in + (size_t)(b*5 + fi) * CF * HWSZ;
    } else {
        inb = scratch_ptr(inSel) + (size_t)eb * Cin * HWSZ;
    }

    float acc0[16], acc1[16];
    #pragma unroll
    for (int i = 0; i < 16; i++) { acc0[i] = 0.f; acc1[i] = 0.f; }

    for (int cb = 0; cb < Cin; cb += 8) {
        // cooperative load: 8 channels x (18 x 34) tile with zero-pad
        for (int idx = tid; idx < 8*18*34; idx += 256) {
            int ci = idx / (18*34);
            int r  = (idx / 34) % 18;
            int c  = idx % 34;
            int gy = oy0 + r - 1;
            int gx = ox0 + c - 1;
            float v = 0.f;
            if (gy >= 0 && gy < HH && gx >= 0 && gx < WW) {
                int ch = cb + ci;
                const float* p;
                if (inMode == 1)
                    p = (ch < CF) ? (ref + (size_t)ch*HWSZ) : (supp + (size_t)(ch-CF)*HWSZ);
                else
                    p = inb + (size_t)ch*HWSZ;
                v = p[gy*WW + gx];
            }
            s_in[ci][r][c] = v;
        }
        // weights: 16 oc x 8 ci x 9
        for (int idx = tid; idx < 16*8*9; idx += 256) {
            int oc = idx / 72;
            int ci = (idx % 72) / 9;
            int k  = idx % 9;
            int o = ocBase + oc;
            float v = 0.f;
            if (o < Cout) v = w[((size_t)o*Cin + (cb+ci))*9 + k];
            s_w[oc][ci][k] = v;
        }
        __syncthreads();

        #pragma unroll
        for (int ci = 0; ci < 8; ci++) {
            #pragma unroll
            for (int kk = 0; kk < 9; kk++) {
                const int ky = kk / 3, kx = kk % 3;
                float v0 = s_in[ci][ty + ky][tx + kx];
                float v1 = s_in[ci][ty + 8 + ky][tx + kx];
                #pragma unroll
                for (int oc = 0; oc < 16; oc++) {
                    float wv = s_w[oc][ci][kk];
                    acc0[oc] += v0 * wv;
                    acc1[oc] += v1 * wv;
                }
            }
        }
        __syncthreads();
    }

    int gx = ox0 + tx;
    int gy0 = oy0 + ty, gy1 = gy0 + 8;
    float* ob;
    if (outMode == 1) ob = ext_out + (size_t)(b*5 + fi) * 3 * HWSZ;
    else              ob = scratch_ptr(outSel) + (size_t)eb * Cout * HWSZ;

    #pragma unroll
    for (int oc = 0; oc < 16; oc++) {
        int o = ocBase + oc;
        if (o < Cout) {
            float bv = bias[o];
            ob[(size_t)o*HWSZ + gy0*WW + gx] = acc0[oc] + bv;
            ob[(size_t)o*HWSZ + gy1*WW + gx] = acc1[oc] + bv;
        }
    }
}

// ---------------- deformable conv (dg=8, Cg=8, K=3) ----------------
// xMode: 0 = x = scratch[xSel] + eb*64*HW ; 1 = x is supp read from pf (ext_x)
__global__ void __launch_bounds__(128) dconv_kernel(
    const float* __restrict__ ext_x,
    const float* __restrict__ bias,
    int xMode, int xSel, int wIdx, int outSel)
{
    int tid = threadIdx.x;
    int tx = tid & 15, ty = tid >> 4;          // 16 x 8 tile
    int eb = blockIdx.z;
    int b, fi; eb_map(eb, b, fi);
    int gx = blockIdx.x * 16 + tx;
    int gy = blockIdx.y * 8 + ty;
    int p = gy * WW + gx;

    const float* x = (xMode == 1) ? ext_x + (size_t)(b*5 + fi) * CF * HWSZ
                                  : scratch_ptr(xSel) + (size_t)eb * CF * HWSZ;
    const float* off = g_off + (size_t)eb * COFF * HWSZ + p;
    const float* wT  = g_wT + (size_t)wIdx * WSTEP;   // [(ci*9+k)*64 + o]

    float acc[64];
    #pragma unroll
    for (int o = 0; o < 64; o++) acc[o] = 0.f;

    #pragma unroll 1
    for (int g = 0; g < 8; g++) {
        #pragma unroll 1
        for (int k = 0; k < 9; k++) {
            float oy = off[(size_t)((g*9 + k)*2 + 0) * HWSZ];
            float ox = off[(size_t)((g*9 + k)*2 + 1) * HWSZ];
            float py = (float)gy + (float)(k/3 - 1) + oy;
            float px = (float)gx + (float)(k%3 - 1) + ox;
            float fy = floorf(py), fx = floorf(px);
            float wy = py - fy,  wx = px - fx;
            int iy0 = (int)fy, ix0 = (int)fx;
            int iy1 = iy0 + 1, ix1 = ix0 + 1;
            float my0 = (iy0 >= 0 && iy0 < HH) ? 1.f : 0.f;
            float my1 = (iy1 >= 0 && iy1 < HH) ? 1.f : 0.f;
            float mx0 = (ix0 >= 0 && ix0 < WW) ? 1.f : 0.f;
            float mx1 = (ix1 >= 0 && ix1 < WW) ? 1.f : 0.f;
            int cy0 = min(max(iy0, 0), HH-1);
            int cy1 = min(max(iy1, 0), HH-1);
            int cx0 = min(max(ix0, 0), WW-1);
            int cx1 = min(max(ix1, 0), WW-1);
            int p00 = cy0*WW + cx0, p01 = cy0*WW + cx1;
            int p10 = cy1*WW + cx0, p11 = cy1*WW + cx1;
            float w00 = (1.f - wy) * (1.f - wx) * my0 * mx0;
            float w01 = (1.f - wy) * wx         * my0 * mx1;
            float w10 = wy         * (1.f - wx) * my1 * mx0;
            float w11 = wy         * wx         * my1 * mx1;

            #pragma unroll
            for (int c = 0; c < 8; c++) {
                const float* ch = x + (size_t)(g*8 + c) * HWSZ;
                float s = ch[p00]*w00 + ch[p01]*w01 + ch[p10]*w10 + ch[p11]*w11;
                const float4* wtc = (const float4*)(wT + ((size_t)((g*8 + c)*9 + k)) * 64);
                #pragma unroll
                for (int o4 = 0; o4 < 16; o4++) {
                    float4 wv = wtc[o4];
                    acc[o4*4+0] += s * wv.x;
                    acc[o4*4+1] += s * wv.y;
                    acc[o4*4+2] += s * wv.z;
                    acc[o4*4+3] += s * wv.w;
                }
            }
        }
    }

    float* ob = scratch_ptr(outSel) + (size_t)eb * CF * HWSZ + p;
    #pragma unroll
    for (int o = 0; o < 64; o++) ob[(size_t)o * HWSZ] = acc[o] + bias[o];
}

// ---------------- dconv weight transpose: OIHW -> [(ci*9+k)][o] ----------------
__global__ void wtrans_kernel(const float* __restrict__ w, int wIdx) {
    int i = blockIdx.x * 256 + threadIdx.x;
    if (i < 64*576) {
        int o = i / 576;
        int r = i % 576;
        g_wT[(size_t)wIdx*WSTEP + (size_t)r*64 + o] = w[i];
    }
}

// ---------------- center frame passthrough ----------------
__global__ void center_kernel(const float* __restrict__ xc, float* __restrict__ out) {
    int i = blockIdx.x * 256 + threadIdx.x;
    const int total = 2*3*HWSZ;
    if (i < total) {
        int b = i / (3*HWSZ);
        int r = i % (3*HWSZ);
        out[(size_t)(b*5 + 2)*3*HWSZ + r] = xc[i];
    }
}

// ---------------- launch (pure kernel launches; nothing else) ----------------
extern "C" void kernel_launch(void* const* d_in, const int* in_sizes, int n_in,
                              void* d_out, int out_size)
{
    const float* pf     = (const float*)d_in[0];
    const float* xc     = (const float*)d_in[1];
    const float* cr_w   = (const float*)d_in[2];
    const float* cr_b   = (const float*)d_in[3];
    const float* off1_w = (const float*)d_in[4];
    const float* off1_b = (const float*)d_in[5];
    const float* dc1_w  = (const float*)d_in[6];
    const float* dc1_b  = (const float*)d_in[7];
    const float* off2_w = (const float*)d_in[8];
    const float* off2_b = (const float*)d_in[9];
    const float* dc2_w  = (const float*)d_in[10];
    const float* dc2_b  = (const float*)d_in[11];
    const float* off3_w = (const float*)d_in[12];
    const float* off3_b = (const float*)d_in[13];
    const float* dc3_w  = (const float*)d_in[14];
    const float* dc3_b  = (const float*)d_in[15];
    const float* off4_w = (const float*)d_in[16];
    const float* off4_b = (const float*)d_in[17];
    const float* dc4_w  = (const float*)d_in[18];
    const float* dc4_b  = (const float*)d_in[19];
    const float* rec_w  = (const float*)d_in[20];
    const float* rec_b  = (const float*)d_in[21];
    float* out = (float*)d_out;

    dim3 tb(256);
    // transpose the 4 dconv weight tensors into g_wT
    wtrans_kernel<<<144, tb>>>(dc1_w, 0);
    wtrans_kernel<<<144, tb>>>(dc2_w, 1);
    wtrans_kernel<<<144, tb>>>(dc3_w, 2);
    wtrans_kernel<<<144, tb>>>(dc4_w, 3);

    // center frame
    center_kernel<<<(2*3*HWSZ + 255)/256, tb>>>(xc, out);

    auto conv = [&](const float* ein, const float* w, const float* bsrc, float* eout,
                    int Cin, int Cout, int inMode, int outMode, int inSel, int outSel) {
        int ocg = (Cout + 15) >> 4;
        dim3 grid(WW/32, HH/16, EBN * ocg);
        conv3x3_kernel<<<grid, 256>>>(ein, w, bsrc, eout, Cin, Cout,
                                      inMode, outMode, inSel, outSel);
    };
    auto dconv = [&](const float* ex, const float* bsrc,
                     int xMode, int xSel, int wIdx, int outSel) {
        dim3 grid(WW/16, HH/8, EBN);
        dconv_kernel<<<grid, 128>>>(ex, bsrc, xMode, xSel, wIdx, outSel);
    };

    // fea0 = conv(concat(ref,supp))
    conv(pf, cr_w, cr_b, nullptr, 2*CF, CF, 1, 0, 0, 0);
    // off = off1(fea0); fea1 = dconv(fea0, off)
    conv(nullptr, off1_w, off1_b, nullptr, CF, COFF, 0, 0, 0, 2);
    dconv(nullptr, dc1_b, 0, 0, 0, 1);
    // off = off2(fea1); fea0 = dconv(fea1, off)
    conv(nullptr, off2_w, off2_b, nullptr, CF, COFF, 0, 0, 1, 2);
    dconv(nullptr, dc2_b, 0, 1, 1, 0);
    // off = off3(fea0); fea1 = dconv(supp, off)
    conv(nullptr, off3_w, off3_b, nullptr, CF, COFF, 0, 0, 0, 2);
    dconv(pf, dc3_b, 1, 0, 2, 1);
    // off = off4(fea1); fea0 = dconv(fea1, off)
    conv(nullptr, off4_w, off4_b, nullptr, CF, COFF, 0, 0, 1, 2);
    dconv(nullptr, dc4_b, 0, 1, 3, 0);
    // out = rec(fea0)
    conv(nullptr, rec_w, rec_b, out, CF, 3, 0, 1, 0, 0);
}